// round 10
// baseline (speedup 1.0000x reference)
#include <cuda_runtime.h>
#include <cstdint>
#include <math.h>

#define BATCH 64
#define SEQ   2048
#define INP   256
#define HID   512
#define NCTA  128
#define BGR   8      // batches per CTA
#define JGR   32     // hidden columns per CTA

// ---------------- scratch (no allocations allowed) ----------------
// wx stored scan-friendly: g_wx[((s*NCTA)+cta)*256 + q] where q is the
// thread-permuted tile index (thread t of CTA cta reads element t at step s).
__device__ float    g_wx[(size_t)SEQ * NCTA * 256];
__device__ float    g_hbuf[2 * BATCH * HID];        // double-buffered hidden state
__device__ unsigned g_flags[NCTA];                  // per-CTA epoch flags (monotone across replays)

// ---------------- packed fp32x2 FMA helpers (phase 1 only) ----------------
__device__ __forceinline__ void fma2(unsigned long long &d, unsigned long long a, unsigned long long b) {
    asm("fma.rn.f32x2 %0, %1, %2, %0;" : "+l"(d) : "l"(a), "l"(b));
}
__device__ __forceinline__ unsigned long long pack2(float lo, float hi) {
    unsigned long long r;
    asm("mov.b64 %0, {%1, %2};" : "=l"(r) : "f"(lo), "f"(hi));
    return r;
}
__device__ __forceinline__ float lo2(unsigned long long v) { return __uint_as_float((unsigned)v); }
__device__ __forceinline__ float hi2(unsigned long long v) { return __uint_as_float((unsigned)(v >> 32)); }

// ---------------- sync ops: relaxed poll + single acquire fence ----------------
__device__ __forceinline__ unsigned ldrelax(const unsigned* p) {
    unsigned v;
    asm volatile("ld.relaxed.gpu.global.u32 %0, [%1];" : "=r"(v) : "l"(p) : "memory");
    return v;
}
__device__ __forceinline__ void fence_acq() {
    asm volatile("fence.acq_rel.gpu;" ::: "memory");
}
__device__ __forceinline__ void strel(unsigned* p, unsigned v) {
    asm volatile("st.release.gpu.global.u32 [%0], %1;" :: "l"(p), "r"(v) : "memory");
}

// =====================================================================
// Phase 1: wx[b,s,:] = x[b,s,:] @ W + Wb      (M=131072, N=512, K=256)
// Same GEMM as before; epilogue stores into the scan-permuted layout.
// 64-row m-tiles never cross a batch boundary (64 | 2048).
// =====================================================================
#define P1_BM 64
#define P1_BN 64
#define P1_BK 64

__global__ __launch_bounds__(256) void wx_kernel(const float* __restrict__ X,
                                                 const float* __restrict__ W,
                                                 const float* __restrict__ Wb) {
    __shared__ float Xs[P1_BM][P1_BK + 4];
    __shared__ float Ws[P1_BK][P1_BN + 4];

    const int t    = threadIdx.x;
    const int mpos = t >> 4;
    const int npos = t & 15;
    const int m0   = blockIdx.x * P1_BM;
    const int n0   = blockIdx.y * P1_BN;

    unsigned long long acc[4][2];
#pragma unroll
    for (int i = 0; i < 4; i++) { acc[i][0] = 0ull; acc[i][1] = 0ull; }

    for (int k0 = 0; k0 < INP; k0 += P1_BK) {
#pragma unroll
        for (int i = t; i < (P1_BM * P1_BK) / 4; i += 256) {
            int r = i >> 4;
            int c = i & 15;
            float4 v = *(const float4*)(X + (size_t)(m0 + r) * INP + k0 + c * 4);
            *(float4*)(&Xs[r][c * 4]) = v;
        }
#pragma unroll
        for (int i = t; i < (P1_BK * P1_BN) / 4; i += 256) {
            int r = i >> 4;
            int c = i & 15;
            float4 v = *(const float4*)(W + (size_t)(k0 + r) * HID + n0 + c * 4);
            *(float4*)(&Ws[r][c * 4]) = v;
        }
        __syncthreads();

#pragma unroll
        for (int k = 0; k < P1_BK; k++) {
            ulonglong2 w = *(const ulonglong2*)(&Ws[k][npos * 4]);
#pragma unroll
            for (int i = 0; i < 4; i++) {
                float a = Xs[mpos * 4 + i][k];
                unsigned long long ad = pack2(a, a);
                fma2(acc[i][0], ad, w.x);
                fma2(acc[i][1], ad, w.y);
            }
        }
        __syncthreads();
    }

    // epilogue: permuted scan-friendly store
    // b constant per CTA tile; scan thread t = (jj>>2)*32 + bi*4 + (jj&3)
    const int b  = m0 / SEQ;
    const int s0 = m0 % SEQ;
    const int bg = b >> 3, bi = b & 7;
    const int n  = n0 + npos * 4;
    const int jg = n >> 5;
    const int jj = n & 31;
    const int q  = (jj >> 2) * 32 + bi * 4;        // +jl via float4 lanes
    const int cta = bg * 16 + jg;

    float4 bb = *(const float4*)(Wb + n);
#pragma unroll
    for (int i = 0; i < 4; i++) {
        float4 v;
        v.x = lo2(acc[i][0]) + bb.x;
        v.y = hi2(acc[i][0]) + bb.y;
        v.z = lo2(acc[i][1]) + bb.z;
        v.w = hi2(acc[i][1]) + bb.w;
        const int s = s0 + mpos * 4 + i;
        *(float4*)(g_wx + ((size_t)s * NCTA + cta) * 256 + q) = v;
    }
}

// =====================================================================
// Phase 2: persistent RNN scan — scalar FFMA, group-local relaxed flags.
// 128 CTAs: cta = bg*16+jg -> 8 batches x 32 hidden cols; dependency of
// (bg,jg) is only on the 16 CTAs sharing bg (flags contiguous per group).
// Sync: producers st.release.gpu their flag; consumers poll with
// ld.relaxed.gpu and issue ONE fence.acq_rel.gpu after success.
// Compute: 8 warps, warp = 8b x 4j outputs, full K split over 32 lanes in
// 4 quads (warp-wide float4 LDS = contiguous conflict-free 512B); scalar
// FFMA (512/lane/step); 5-stage butterfly leaves output L in lane L.
// wx: one fully-coalesced 1KB load per CTA per step (permuted layout),
// issued before the poll so DRAM latency hides under the wait.
// =====================================================================
__global__ __launch_bounds__(256, 1) void rnn_kernel(const float* __restrict__ Uw,
                                                     const float* __restrict__ Ub) {
    extern __shared__ float sm[];
    float* Ush = sm;                  // [JGR][512]  (64 KB)  Ush[j][k] = U[k][j0+j]
    float* hsh = sm + JGR * HID;      // [BGR][512]  (16 KB)

    const int t    = threadIdx.x;
    const int cta  = blockIdx.x;
    const int bg   = cta >> 4;        // matches phase-1 cta = bg*16+jg
    const int jg   = cta & 15;
    const int b0   = bg * BGR;
    const int j0   = jg * JGR;
    const int w    = t >> 5;
    const int lane = t & 31;

    // after butterfly: lane L holds output o = L -> b = L>>2, jl = L&3
    const int ob = lane >> 2;
    const int oj = (w << 2) | (lane & 3);

    const int fidx = cta;                       // flags already group-contiguous
    unsigned* const fgrp = g_flags + bg * 16;
    const unsigned base = g_flags[fidx];        // replay-safe epoch base

    // one-time: U slice transposed -> Ush[j][k] = U[k][j0+j]
    for (int i = t; i < JGR * HID; i += 256) {
        int jj = i & 31;
        int k  = i >> 5;
        Ush[jj * HID + k] = Uw[(size_t)k * HID + j0 + jj];
    }
    const float ubj = Ub[j0 + oj];
    const float* const wxbase = g_wx + (size_t)cta * 256 + t;
    __syncthreads();

    for (int s = 0; s < SEQ; s++) {
        // coalesced wx prefetch (independent of flags; hides DRAM under poll)
        const float wxv = wxbase[(size_t)s * (NCTA * 256)];

        if (s == 0) {
            for (int i = t; i < BGR * HID; i += 256) hsh[i] = 0.0f;
        } else {
            // relaxed group poll (lanes 0..15), then ONE acquire fence
            const unsigned tgt = base + (unsigned)s;
            unsigned v = tgt;
            if (lane < 16) v = ldrelax(fgrp + lane);
            while (__any_sync(0xffffffffu, (int)(v - tgt) < 0)) {
                if (lane < 16 && (int)(v - tgt) < 0) v = ldrelax(fgrp + lane);
            }
            fence_acq();
            // stage this CTA's 8 h rows (16KB) from L2 into SMEM
            const float* hsrc = g_hbuf + (s & 1) * (BATCH * HID) + (size_t)b0 * HID;
            for (int i = t; i < (BGR * HID) / 4; i += 256)
                ((float4*)hsh)[i] = ((const float4*)hsrc)[i];
        }
        __syncthreads();

        // scalar-FFMA register tile: 8b x 4j, K over lanes in 4 quads
        float acc[32];
#pragma unroll
        for (int o = 0; o < 32; o++) acc[o] = 0.0f;

#pragma unroll
        for (int qi = 0; qi < 4; qi++) {
            const int kb = qi * 128 + lane * 4;
            float4 hq[8], uq[4];
#pragma unroll
            for (int b = 0; b < 8; b++)
                hq[b] = *(const float4*)(hsh + b * HID + kb);
#pragma unroll
            for (int j = 0; j < 4; j++)
                uq[j] = *(const float4*)(Ush + (w * 4 + j) * HID + kb);
#pragma unroll
            for (int b = 0; b < 8; b++)
#pragma unroll
                for (int j = 0; j < 4; j++) {
                    float a = acc[b * 4 + j];
                    a = fmaf(hq[b].x, uq[j].x, a);
                    a = fmaf(hq[b].y, uq[j].y, a);
                    a = fmaf(hq[b].z, uq[j].z, a);
                    a = fmaf(hq[b].w, uq[j].w, a);
                    acc[b * 4 + j] = a;
                }
        }

        // butterfly-reduce across lanes (output o ends in lane o)
#define BFLY_STAGE(OFF, NKEEP)                                              \
        do {                                                                \
            const bool up = (lane & (OFF)) != 0;                            \
            _Pragma("unroll")                                               \
            for (int i = 0; i < (NKEEP); i++) {                             \
                float send = up ? acc[i] : acc[i + (NKEEP)];                \
                float recv = __shfl_xor_sync(0xffffffffu, send, (OFF));     \
                acc[i] = (up ? acc[i + (NKEEP)] : acc[i]) + recv;           \
            }                                                               \
        } while (0)

        BFLY_STAGE(16, 16);
        BFLY_STAGE(8, 8);
        BFLY_STAGE(4, 4);
        BFLY_STAGE(2, 2);
        BFLY_STAGE(1, 1);
#undef BFLY_STAGE

        float hnew = tanhf(wxv + ubj + acc[0]);
        g_hbuf[((s + 1) & 1) * (BATCH * HID) + (size_t)(b0 + ob) * HID + (j0 + oj)] = hnew;

        // order all h stores before the release; protect hsh for next stage
        __syncthreads();
        if (t == 0) strel(g_flags + fidx, base + (unsigned)s + 1u);
    }
}

// =====================================================================
// Phase 3: out = sigmoid(h_T @ V + Vb).  h_T lands in g_hbuf buffer 0.
// =====================================================================
__global__ __launch_bounds__(128) void out_kernel(const float* __restrict__ Vw,
                                                  const float* __restrict__ Vb,
                                                  float* __restrict__ out) {
    const int bb = blockIdx.x;
    const int t  = threadIdx.x;
    const float* h = g_hbuf + (size_t)bb * HID;

    float a0 = 0.f, a1 = 0.f;
    for (int k = t; k < HID; k += 128) {
        float hv = h[k];
        a0 += hv * Vw[k * 2 + 0];
        a1 += hv * Vw[k * 2 + 1];
    }
#pragma unroll
    for (int off = 16; off > 0; off >>= 1) {
        a0 += __shfl_down_sync(0xffffffffu, a0, off);
        a1 += __shfl_down_sync(0xffffffffu, a1, off);
    }
    __shared__ float p0[4], p1[4];
    if ((t & 31) == 0) { p0[t >> 5] = a0; p1[t >> 5] = a1; }
    __syncthreads();
    if (t == 0) {
        float s0 = p0[0] + p0[1] + p0[2] + p0[3] + Vb[0];
        float s1 = p1[0] + p1[1] + p1[2] + p1[3] + Vb[1];
        out[bb * 2 + 0] = 1.f / (1.f + expf(-s0));
        out[bb * 2 + 1] = 1.f / (1.f + expf(-s1));
    }
}

// =====================================================================
extern "C" void kernel_launch(void* const* d_in, const int* in_sizes, int n_in,
                              void* d_out, int out_size) {
    const float* x  = (const float*)d_in[0];
    const float* Ww = (const float*)d_in[1];
    const float* Wb = (const float*)d_in[2];
    const float* Uw = (const float*)d_in[3];
    const float* Ub = (const float*)d_in[4];
    const float* Vw = (const float*)d_in[5];
    const float* Vb = (const float*)d_in[6];
    float* out = (float*)d_out;

    // Phase 1: input projections for all timesteps (scan-permuted layout)
    dim3 g1((BATCH * SEQ) / P1_BM, HID / P1_BN);
    wx_kernel<<<g1, 256>>>(x, Ww, Wb);

    // Phase 2: persistent scan (80 KB dynamic smem)
    size_t smem2 = (size_t)(JGR + BGR) * HID * sizeof(float);
    cudaFuncSetAttribute(rnn_kernel, cudaFuncAttributeMaxDynamicSharedMemorySize, (int)smem2);
    rnn_kernel<<<NCTA, 256, smem2>>>(Uw, Ub);

    // Phase 3: readout
    out_kernel<<<BATCH, 128>>>(Vw, Vb, out);
}

// round 11
// speedup vs baseline: 3.4875x; 3.4875x over previous
#include <cuda_runtime.h>
#include <cstdint>
#include <math.h>

#define BATCH 64
#define SEQ   2048
#define INP   256
#define HID   512
#define NCTA  128
#define BGR   8      // batches per CTA
#define JGR   32     // hidden columns per CTA

// ---------------- scratch (no allocations allowed) ----------------
// wx stored scan-friendly: g_wx[((s*NCTA)+cta)*256 + t] -> thread t of CTA cta
// reads exactly its own element at step s (fully coalesced 1KB per CTA).
__device__ float    g_wx[(size_t)SEQ * NCTA * 256];
__device__ float    g_hbuf[2 * BATCH * HID];        // double-buffered hidden state
__device__ unsigned g_flags[NCTA];                  // per-CTA epoch flags (monotone across replays)

// ---------------- packed fp32x2 FMA helpers (FFMA2) ----------------
__device__ __forceinline__ void fma2(unsigned long long &d, unsigned long long a, unsigned long long b) {
    asm("fma.rn.f32x2 %0, %1, %2, %0;" : "+l"(d) : "l"(a), "l"(b));
}
__device__ __forceinline__ unsigned long long pack2(float lo, float hi) {
    unsigned long long r;
    asm("mov.b64 %0, {%1, %2};" : "=l"(r) : "f"(lo), "f"(hi));
    return r;
}
__device__ __forceinline__ float lo2(unsigned long long v) { return __uint_as_float((unsigned)v); }
__device__ __forceinline__ float hi2(unsigned long long v) { return __uint_as_float((unsigned)(v >> 32)); }

// ---------------- sync ops (NO fences of scope>=cluster in the step path!) ----------------
__device__ __forceinline__ unsigned ldacq(const unsigned* p) {
    unsigned v;
    asm volatile("ld.acquire.gpu.global.u32 %0, [%1];" : "=r"(v) : "l"(p) : "memory");
    return v;
}
__device__ __forceinline__ void strel(unsigned* p, unsigned v) {
    asm volatile("st.release.gpu.global.u32 [%0], %1;" :: "l"(p), "r"(v) : "memory");
}

// =====================================================================
// Phase 1: wx[b,s,:] = x[b,s,:] @ W + Wb      (M=131072, N=512, K=256)
// Epilogue stores into the scan-permuted layout (validated in R10,
// rel_err 7.5e-8). 64-row m-tiles never cross a batch boundary.
// =====================================================================
#define P1_BM 64
#define P1_BN 64
#define P1_BK 64

__global__ __launch_bounds__(256) void wx_kernel(const float* __restrict__ X,
                                                 const float* __restrict__ W,
                                                 const float* __restrict__ Wb) {
    __shared__ float Xs[P1_BM][P1_BK + 4];
    __shared__ float Ws[P1_BK][P1_BN + 4];

    const int t    = threadIdx.x;
    const int mpos = t >> 4;
    const int npos = t & 15;
    const int m0   = blockIdx.x * P1_BM;
    const int n0   = blockIdx.y * P1_BN;

    unsigned long long acc[4][2];
#pragma unroll
    for (int i = 0; i < 4; i++) { acc[i][0] = 0ull; acc[i][1] = 0ull; }

    for (int k0 = 0; k0 < INP; k0 += P1_BK) {
#pragma unroll
        for (int i = t; i < (P1_BM * P1_BK) / 4; i += 256) {
            int r = i >> 4;
            int c = i & 15;
            float4 v = *(const float4*)(X + (size_t)(m0 + r) * INP + k0 + c * 4);
            *(float4*)(&Xs[r][c * 4]) = v;
        }
#pragma unroll
        for (int i = t; i < (P1_BK * P1_BN) / 4; i += 256) {
            int r = i >> 4;
            int c = i & 15;
            float4 v = *(const float4*)(W + (size_t)(k0 + r) * HID + n0 + c * 4);
            *(float4*)(&Ws[r][c * 4]) = v;
        }
        __syncthreads();

#pragma unroll
        for (int k = 0; k < P1_BK; k++) {
            ulonglong2 w = *(const ulonglong2*)(&Ws[k][npos * 4]);
#pragma unroll
            for (int i = 0; i < 4; i++) {
                float a = Xs[mpos * 4 + i][k];
                unsigned long long ad = pack2(a, a);
                fma2(acc[i][0], ad, w.x);
                fma2(acc[i][1], ad, w.y);
            }
        }
        __syncthreads();
    }

    // epilogue: permuted scan-friendly store
    const int b  = m0 / SEQ;
    const int s0 = m0 % SEQ;
    const int bg = b >> 3, bi = b & 7;
    const int n  = n0 + npos * 4;
    const int jg = n >> 5;
    const int jj = n & 31;
    const int q  = (jj >> 2) * 32 + bi * 4;        // +jl via float4 lanes
    const int cta = bg * 16 + jg;

    float4 bb = *(const float4*)(Wb + n);
#pragma unroll
    for (int i = 0; i < 4; i++) {
        float4 v;
        v.x = lo2(acc[i][0]) + bb.x;
        v.y = hi2(acc[i][0]) + bb.y;
        v.z = lo2(acc[i][1]) + bb.z;
        v.w = hi2(acc[i][1]) + bb.w;
        const int s = s0 + mpos * 4 + i;
        *(float4*)(g_wx + ((size_t)s * NCTA + cta) * 256 + q) = v;
    }
}

// =====================================================================
// Phase 2: persistent RNN scan — FFMA2, U-IN-REGISTERS, single-warp poll.
// 128 CTAs: cta = bg*16+jg -> 8 batches x 32 hidden cols; dependency of
// (bg,jg) is only on the 16 CTAs sharing bg (flags contiguous per group).
// Sync: ONLY warp 0 polls the 16 group flags with ld.acquire.gpu (8x fewer
// strong loads to the contended L2 lines than R7), then __syncthreads
// releases the other warps (scoped-acquire -> bar visibility chain).
// Compute: warp = 8b x 4j outputs, K split over 32 lanes in 4 quads.
// U slice lives permanently in registers (16 ulonglong2 per lane, loaded
// once): inner loop does ONLY h loads from smem -> 1024 smem wavefronts
// per step, balancing the 1024-cyc FFMA2 issue floor. 5-stage butterfly
// leaves output L in lane L.
// =====================================================================
__global__ __launch_bounds__(256, 1) void rnn_kernel(const float* __restrict__ Uw,
                                                     const float* __restrict__ Ub) {
    __shared__ float hsh[BGR * HID];   // 16 KB static

    const int t    = threadIdx.x;
    const int cta  = blockIdx.x;
    const int bg   = cta >> 4;        // matches phase-1 cta = bg*16+jg
    const int jg   = cta & 15;
    const int b0   = bg * BGR;
    const int j0   = jg * JGR;
    const int w    = t >> 5;
    const int lane = t & 31;

    // after butterfly: lane L holds output o = L -> b = L>>2, jl = L&3
    const int ob = lane >> 2;
    const int oj = (w << 2) | (lane & 3);

    unsigned* const fgrp = g_flags + bg * 16;
    const unsigned base = g_flags[cta];          // replay-safe epoch base

    // ---- one-time: load this lane's U slice into registers ----
    // ureg[qi][j] = (U[kb][jc], U[kb+1][jc]),(U[kb+2][jc], U[kb+3][jc])
    // with kb = qi*128 + lane*4, jc = j0 + w*4 + j.
    ulonglong2 ureg[4][4];
#pragma unroll
    for (int qi = 0; qi < 4; qi++) {
        const int kb = qi * 128 + lane * 4;
#pragma unroll
        for (int j = 0; j < 4; j++) {
            const float* up = Uw + (size_t)kb * HID + (j0 + w * 4 + j);
            float u0 = up[0];
            float u1 = up[HID];
            float u2 = up[2 * HID];
            float u3 = up[3 * HID];
            ureg[qi][j].x = pack2(u0, u1);
            ureg[qi][j].y = pack2(u2, u3);
        }
    }
    const float ubj = Ub[j0 + oj];
    const float* const wxbase = g_wx + (size_t)cta * 256 + t;

    for (int s = 0; s < SEQ; s++) {
        // coalesced wx prefetch (independent of flags; hides under the wait)
        const float wxv = wxbase[(size_t)s * (NCTA * 256)];

        if (s == 0) {
            for (int i = t; i < BGR * HID; i += 256) hsh[i] = 0.0f;
            __syncthreads();
        } else {
            // ---- single-warp acquire poll of the 16 group flags ----
            if (w == 0) {
                const unsigned tgt = base + (unsigned)s;
                unsigned v = tgt;
                if (lane < 16) v = ldacq(fgrp + lane);
                while (__any_sync(0xffffffffu, (int)(v - tgt) < 0)) {
                    if (lane < 16 && (int)(v - tgt) < 0) v = ldacq(fgrp + lane);
                }
            }
            __syncthreads();   // releases warps 1..7; extends acquire to CTA
            // stage this CTA's 8 h rows (16KB) from L2 into SMEM
            const float* hsrc = g_hbuf + (s & 1) * (BATCH * HID) + (size_t)b0 * HID;
            for (int i = t; i < (BGR * HID) / 4; i += 256)
                ((float4*)hsh)[i] = ((const float4*)hsrc)[i];
            __syncthreads();
        }

        // FFMA2 register tile: 8b x 4j, K over lanes in 4 quads; U from regs
        unsigned long long acc[32];
#pragma unroll
        for (int o = 0; o < 32; o++) acc[o] = 0ull;

#pragma unroll
        for (int qi = 0; qi < 4; qi++) {
            const int kb = qi * 128 + lane * 4;
            ulonglong2 hq[8];
#pragma unroll
            for (int b = 0; b < 8; b++)
                hq[b] = *(const ulonglong2*)(hsh + b * HID + kb);
#pragma unroll
            for (int b = 0; b < 8; b++)
#pragma unroll
                for (int j = 0; j < 4; j++) {
                    fma2(acc[b * 4 + j], hq[b].x, ureg[qi][j].x);
                    fma2(acc[b * 4 + j], hq[b].y, ureg[qi][j].y);
                }
        }

        // fold k-parity, then butterfly-reduce (output o ends in lane o)
        float v[32];
#pragma unroll
        for (int o = 0; o < 32; o++) v[o] = lo2(acc[o]) + hi2(acc[o]);

#define BFLY_STAGE(OFF, NKEEP)                                              \
        do {                                                                \
            const bool up = (lane & (OFF)) != 0;                            \
            _Pragma("unroll")                                               \
            for (int i = 0; i < (NKEEP); i++) {                             \
                float send = up ? v[i] : v[i + (NKEEP)];                    \
                float recv = __shfl_xor_sync(0xffffffffu, send, (OFF));     \
                v[i] = (up ? v[i + (NKEEP)] : v[i]) + recv;                 \
            }                                                               \
        } while (0)

        BFLY_STAGE(16, 16);
        BFLY_STAGE(8, 8);
        BFLY_STAGE(4, 4);
        BFLY_STAGE(2, 2);
        BFLY_STAGE(1, 1);
#undef BFLY_STAGE

        float hnew = tanhf(wxv + ubj + v[0]);
        g_hbuf[((s + 1) & 1) * (BATCH * HID) + (size_t)(b0 + ob) * HID + (j0 + oj)] = hnew;

        // order all h stores before the release; protect hsh for next stage
        __syncthreads();
        if (t == 0) strel(g_flags + cta, base + (unsigned)s + 1u);
    }
}

// =====================================================================
// Phase 3: out = sigmoid(h_T @ V + Vb).  h_T lands in g_hbuf buffer 0.
// =====================================================================
__global__ __launch_bounds__(128) void out_kernel(const float* __restrict__ Vw,
                                                  const float* __restrict__ Vb,
                                                  float* __restrict__ out) {
    const int bb = blockIdx.x;
    const int t  = threadIdx.x;
    const float* h = g_hbuf + (size_t)bb * HID;

    float a0 = 0.f, a1 = 0.f;
    for (int k = t; k < HID; k += 128) {
        float hv = h[k];
        a0 += hv * Vw[k * 2 + 0];
        a1 += hv * Vw[k * 2 + 1];
    }
#pragma unroll
    for (int off = 16; off > 0; off >>= 1) {
        a0 += __shfl_down_sync(0xffffffffu, a0, off);
        a1 += __shfl_down_sync(0xffffffffu, a1, off);
    }
    __shared__ float p0[4], p1[4];
    if ((t & 31) == 0) { p0[t >> 5] = a0; p1[t >> 5] = a1; }
    __syncthreads();
    if (t == 0) {
        float s0 = p0[0] + p0[1] + p0[2] + p0[3] + Vb[0];
        float s1 = p1[0] + p1[1] + p1[2] + p1[3] + Vb[1];
        out[bb * 2 + 0] = 1.f / (1.f + expf(-s0));
        out[bb * 2 + 1] = 1.f / (1.f + expf(-s1));
    }
}

// =====================================================================
extern "C" void kernel_launch(void* const* d_in, const int* in_sizes, int n_in,
                              void* d_out, int out_size) {
    const float* x  = (const float*)d_in[0];
    const float* Ww = (const float*)d_in[1];
    const float* Wb = (const float*)d_in[2];
    const float* Uw = (const float*)d_in[3];
    const float* Ub = (const float*)d_in[4];
    const float* Vw = (const float*)d_in[5];
    const float* Vb = (const float*)d_in[6];
    float* out = (float*)d_out;

    // Phase 1: input projections for all timesteps (scan-permuted layout)
    dim3 g1((BATCH * SEQ) / P1_BM, HID / P1_BN);
    wx_kernel<<<g1, 256>>>(x, Ww, Wb);

    // Phase 2: persistent scan (16 KB static smem, U in registers)
    rnn_kernel<<<NCTA, 256>>>(Uw, Ub);

    // Phase 3: readout
    out_kernel<<<BATCH, 128>>>(Vw, Vb, out);
}